// round 8
// baseline (speedup 1.0000x reference)
#include <cuda_runtime.h>

#define CG_TOTAL 1225
#define PAIRS 6
#define WARPS 4   // 128 threads/block, 24 candidate pairs per block
#define FULLM 0xffffffffu

__constant__ int c_cgoff[9] = {0,1,10,35,44,125,350,375,600};

__host__ __device__ constexpr int PFX(int b) {
    const int t[16] = {0,1,2,5,10,11,12,15,20,23,26,35,50,55,60,75};
    return t[b];
}
__host__ __device__ constexpr int CGO(int p) {
    const int t[9] = {0,1,10,35,44,125,350,375,600};
    return t[p];
}

// Local index of each edge within its type-pair sel list.
__device__ int g2b_scratch[524288];

struct KP {
    const float *fe, *fn, *S;
    const int *n1a, *n2a, *einv;
    const float* cg[9];
    const int *sel00, *sel01, *sel11;
    int n00, n01, n11;
    int b1, b2, b3;               // exclusive block-range ends for 00,01,11
    float *out00, *out01, *out10, *out11;
};

__global__ void g2b_kernel(const int* __restrict__ s00, int n00,
                           const int* __restrict__ s01, int n01,
                           const int* __restrict__ s10, int n10,
                           const int* __restrict__ s11, int n11,
                           float* __restrict__ outg)
{
    int total = n00 + n01 + n10 + n11;
    for (int t = blockIdx.x * blockDim.x + threadIdx.x; t < total;
         t += gridDim.x * blockDim.x) {
        const int* s; int loc;
        if (t < n00)                  { s = s00; loc = t; }
        else if (t < n00 + n01)       { s = s01; loc = t - n00; }
        else if (t < n00 + n01 + n10) { s = s10; loc = t - n00 - n01; }
        else                          { s = s11; loc = t - n00 - n01 - n10; }
        int e = __ldg(s + loc);
        g2b_scratch[e] = loc;
        outg[e] = (float)loc;
    }
}

__device__ __forceinline__ void load_cg_shared(float* s_cg, const KP& P) {
    for (int t = threadIdx.x; t < CG_TOTAL; t += blockDim.x) {
        int p = 0;
        #pragma unroll
        for (int q = 1; q < 9; q++) if (t >= c_cgoff[q]) p = q;
        s_cg[t] = __ldg(P.cg[p] + (t - c_cgoff[p]));
    }
}

// One (slot1,slot2) block for a warp's nv compacted pairs.
// Lane l < SZ computes element (li,lj) = (l/W2, l%W2):
//   A = pre_{T1T2}[e]  block (AM1,AM2) elem (li,lj)      [cgA in registers]
//   B = pre_{T2T1}[ie] block (AM2,AM1) elem (lj,li)      [cgB: regs if SZ<15, else streamed from smem]
//   M = 0.5(A+B)
//   out [j][(ROFF+li)*D2 + COFF+lj] = M
//   outT[p][(COFF+lj)*D1 + ROFF+li] = M
template<int L1,int L2,int AM1,int AM2,int ROFF,int COFF,int D1,int D2>
__device__ __forceinline__ void blk(int lane, int nv, int j, int p,
    const float* __restrict__ s_cg,
    const float* __restrict__ s_feA, const float* __restrict__ s_feB,
    float* __restrict__ out, float* __restrict__ outT)
{
    constexpr int W1 = 2*L1+1, W2 = 2*L2+1, SZ = W1*W2;
    constexpr bool STREAMB = (SZ >= 15);   // stream cgB from smem to cap reg pressure
    constexpr int offA = PFX(4*AM1+AM2), offB = PFX(4*AM2+AM1);
    constexpr int A0 = offA & ~3, B0 = offB & ~3;
    constexpr int SA = offA - A0, SB = offB - B0;
    constexpr int NA = (SA + SZ + 3) / 4, NB = (SB + SZ + 3) / 4;

    int li = lane / W2, lj = lane % W2;
    const float* cbs = s_cg + CGO(L2*3+L1) + (lj*W1+li) * SZ;
    float cgA[SZ];
    float cgB[STREAMB ? 1 : SZ];
    if (lane < SZ) {
        const float* ca = s_cg + CGO(L1*3+L2) + lane * SZ;
        #pragma unroll
        for (int k = 0; k < SZ; k++) cgA[k] = ca[k];
        if constexpr (!STREAMB) {
            #pragma unroll
            for (int k = 0; k < SZ; k++) cgB[k] = cbs[k];
        }
    }

    #pragma unroll 2
    for (int pr = 0; pr < nv; pr++) {
        const float4* pa = (const float4*)(s_feA + pr*100 + A0);
        const float4* pb = (const float4*)(s_feB + pr*100 + B0);
        float A = 0.f, B = 0.f;
        #pragma unroll
        for (int v = 0; v < NA; v++) {
            float4 t = pa[v];
            int k0 = 4*v - SA;
            if (k0+0 >= 0 && k0+0 < SZ) A += t.x * cgA[(k0+0 >= 0 && k0+0 < SZ) ? k0+0 : 0];
            if (k0+1 >= 0 && k0+1 < SZ) A += t.y * cgA[(k0+1 >= 0 && k0+1 < SZ) ? k0+1 : 0];
            if (k0+2 >= 0 && k0+2 < SZ) A += t.z * cgA[(k0+2 >= 0 && k0+2 < SZ) ? k0+2 : 0];
            if (k0+3 >= 0 && k0+3 < SZ) A += t.w * cgA[(k0+3 >= 0 && k0+3 < SZ) ? k0+3 : 0];
        }
        #pragma unroll
        for (int v = 0; v < NB; v++) {
            float4 t = pb[v];
            int k0 = 4*v - SB;
            if constexpr (STREAMB) {
                if (k0+0 >= 0 && k0+0 < SZ) B += t.x * cbs[(k0+0 >= 0 && k0+0 < SZ) ? k0+0 : 0];
                if (k0+1 >= 0 && k0+1 < SZ) B += t.y * cbs[(k0+1 >= 0 && k0+1 < SZ) ? k0+1 : 0];
                if (k0+2 >= 0 && k0+2 < SZ) B += t.z * cbs[(k0+2 >= 0 && k0+2 < SZ) ? k0+2 : 0];
                if (k0+3 >= 0 && k0+3 < SZ) B += t.w * cbs[(k0+3 >= 0 && k0+3 < SZ) ? k0+3 : 0];
            } else {
                if (k0+0 >= 0 && k0+0 < SZ) B += t.x * cgB[(k0+0 >= 0 && k0+0 < SZ) ? k0+0 : 0];
                if (k0+1 >= 0 && k0+1 < SZ) B += t.y * cgB[(k0+1 >= 0 && k0+1 < SZ) ? k0+1 : 0];
                if (k0+2 >= 0 && k0+2 < SZ) B += t.z * cgB[(k0+2 >= 0 && k0+2 < SZ) ? k0+2 : 0];
                if (k0+3 >= 0 && k0+3 < SZ) B += t.w * cgB[(k0+3 >= 0 && k0+3 < SZ) ? k0+3 : 0];
            }
        }
        int jp = __shfl_sync(FULLM, j, pr);
        int pp = __shfl_sync(FULLM, p, pr);
        if (lane < SZ) {
            float M = 0.5f * (A + B);
            out [(size_t)jp * (D1*D2) + (ROFF+li)*D2 + (COFF+lj)] = M;
            outT[(size_t)pp * (D1*D2) + (COFF+lj)*D1 + (ROFF+li)] = M;
        }
    }
}

#define BLK(L1,L2,AM1,AM2,RO,CO,D1,D2) \
    blk<L1,L2,AM1,AM2,RO,CO,D1,D2>(lane, nv, j, p, s_cg, s_feA, s_feB, out, outT)

// SAME=true: canonical filter p>=j, outT==out. SAME=false: 01 list, outT=out10.
template<int T1,int T2>
__device__ __forceinline__ void ham_list(int rel, const KP& P,
    const int* __restrict__ sel, int n,
    float* __restrict__ out, float* __restrict__ outT,
    const float* s_cg, float* s_fe)
{
    constexpr bool SAME = (T1 == T2);
    int warp = threadIdx.x >> 5, lane = threadIdx.x & 31;
    float* s_feA = s_fe + warp * (2 * PAIRS * 100);
    float* s_feB = s_feA + PAIRS * 100;
    int base = (rel * WARPS + warp) * PAIRS;
    if (base >= n) return;
    int navail = min(PAIRS, n - base);

    int j = 0, e = 0, ie = 0, p = 0;
    bool v = false;
    if (lane < navail) {
        j  = base + lane;
        e  = __ldg(sel + j);
        ie = __ldg(P.einv + e);
        p  = g2b_scratch[ie];
        v  = SAME ? (p >= j) : true;
    }
    unsigned m = __ballot_sync(FULLM, v);
    int nv = __popc(m);
    if (nv == 0) return;

    // Compact valid pairs to lanes 0..nv-1.
    int sl = (lane < nv) ? __fns(m, 0, lane + 1) : 0;
    j  = __shfl_sync(FULLM, j,  sl);
    e  = __shfl_sync(FULLM, e,  sl);
    ie = __shfl_sync(FULLM, ie, sl);
    p  = __shfl_sync(FULLM, p,  sl);

    // Stage fe rows (with self-edge node-feature add) for both sides.
    for (int r = 0; r < 2 * nv; r++) {
        int pr = r >> 1;
        int eA = __shfl_sync(FULLM, e,  pr);
        int eB = __shfl_sync(FULLM, ie, pr);
        int edge = (r & 1) ? eB : eA;
        float* dst = ((r & 1) ? s_feB : s_feA) + pr * 100;
        int a  = __ldg(P.n1a + edge);
        int bb = __ldg(P.n2a + edge);
        bool self = false;
        if (a == bb) {
            float sx = __ldg(P.S + 3*edge), sy = __ldg(P.S + 3*edge + 1), sz = __ldg(P.S + 3*edge + 2);
            self = (sx*sx + sy*sy + sz*sz) < 1e-12f;
        }
        if (lane < 25) {
            float4 vv = __ldg((const float4*)(P.fe + (size_t)edge * 100) + lane);
            if (self) {
                float4 w = __ldg((const float4*)(P.fn + (size_t)a * 100) + lane);
                vv.x += w.x; vv.y += w.y; vv.z += w.z; vv.w += w.w;
            }
            ((float4*)dst)[lane] = vv;
        }
    }
    __syncwarp();

    // Type slot tables: type0 slots (L,AM,OFF): (0,0,0),(1,2,1)
    //                   type1 slots:            (0,0,0),(0,1,1),(1,2,2),(2,3,5)
    if constexpr (T1 == 0 && T2 == 0) {
        BLK(0,0,0,0, 0,0, 4,4);  BLK(0,1,0,2, 0,1, 4,4);
        BLK(1,0,2,0, 1,0, 4,4);  BLK(1,1,2,2, 1,1, 4,4);
    } else if constexpr (T1 == 0 && T2 == 1) {
        BLK(0,0,0,0, 0,0, 4,10); BLK(0,0,0,1, 0,1, 4,10);
        BLK(0,1,0,2, 0,2, 4,10); BLK(0,2,0,3, 0,5, 4,10);
        BLK(1,0,2,0, 1,0, 4,10); BLK(1,0,2,1, 1,1, 4,10);
        BLK(1,1,2,2, 1,2, 4,10); BLK(1,2,2,3, 1,5, 4,10);
    } else {
        BLK(0,0,0,0, 0,0, 10,10); BLK(0,0,0,1, 0,1, 10,10);
        BLK(0,1,0,2, 0,2, 10,10); BLK(0,2,0,3, 0,5, 10,10);
        BLK(0,0,1,0, 1,0, 10,10); BLK(0,0,1,1, 1,1, 10,10);
        BLK(0,1,1,2, 1,2, 10,10); BLK(0,2,1,3, 1,5, 10,10);
        BLK(1,0,2,0, 2,0, 10,10); BLK(1,0,2,1, 2,1, 10,10);
        BLK(1,1,2,2, 2,2, 10,10); BLK(1,2,2,3, 2,5, 10,10);
        BLK(2,0,3,0, 5,0, 10,10); BLK(2,0,3,1, 5,1, 10,10);
        BLK(2,1,3,2, 5,2, 10,10); BLK(2,2,3,3, 5,5, 10,10);
    }
}

__global__ __launch_bounds__(128, 8) void fused_kernel(KP P) {
    __shared__ __align__(16) float s_cg[(CG_TOTAL + 3) & ~3];
    __shared__ __align__(16) float s_fe[WARPS * 2 * PAIRS * 100];
    load_cg_shared(s_cg, P);
    __syncthreads();

    int b = blockIdx.x;
    if (b < P.b1)       ham_list<0,0>(b,        P, P.sel00, P.n00, P.out00, P.out00, s_cg, s_fe);
    else if (b < P.b2)  ham_list<0,1>(b - P.b1, P, P.sel01, P.n01, P.out01, P.out10, s_cg, s_fe);
    else                ham_list<1,1>(b - P.b2, P, P.sel11, P.n11, P.out11, P.out11, s_cg, s_fe);
}

extern "C" void kernel_launch(void* const* d_in, const int* in_sizes, int n_in,
                              void* d_out, int out_size) {
    KP P;
    P.fn   = (const float*)d_in[0];
    P.fe   = (const float*)d_in[1];
    P.S    = (const float*)d_in[2];
    const int* eidx = (const int*)d_in[3];
    P.einv = (const int*)d_in[5];
    for (int i = 0; i < 9; i++) P.cg[i] = (const float*)d_in[6 + i];
    P.sel00 = (const int*)d_in[15]; P.n00 = in_sizes[15];
    P.sel01 = (const int*)d_in[16]; P.n01 = in_sizes[16];
    const int* sel10 = (const int*)d_in[17]; int n10 = in_sizes[17];
    P.sel11 = (const int*)d_in[18]; P.n11 = in_sizes[18];

    int E = in_sizes[1] / 100;
    P.n1a = eidx;
    P.n2a = eidx + E;

    float* out = (float*)d_out;
    P.out00 = out;
    P.out01 = P.out00 + 16LL  * P.n00;
    P.out10 = P.out01 + 40LL  * P.n01;
    P.out11 = P.out10 + 40LL  * n10;
    float* outg = P.out11 + 100LL * P.n11;

    const int ppb = WARPS * PAIRS;  // 24 candidate pairs per block
    int nb00 = (P.n00 + ppb - 1) / ppb;
    int nb01 = (P.n01 + ppb - 1) / ppb;
    int nb11 = (P.n11 + ppb - 1) / ppb;
    P.b1 = nb00;
    P.b2 = P.b1 + nb01;
    P.b3 = P.b2 + nb11;

    int tot = P.n00 + P.n01 + n10 + P.n11;
    if (tot) g2b_kernel<<<(tot + 255) / 256, 256>>>(P.sel00, P.n00, P.sel01, P.n01,
                                                    sel10, n10, P.sel11, P.n11, outg);
    if (P.b3 > 0) fused_kernel<<<P.b3, 128>>>(P);

    (void)n_in; (void)out_size;
}